// round 14
// baseline (speedup 1.0000x reference)
#include <cuda_runtime.h>
#include <cuda_fp16.h>
#include <cstdint>

#define DEVINL static __device__ __forceinline__

#define N_EDGES 600000
#define N_NODES 50000
#define ETILES 4688     // ceil(600000/128)
#define NTILES 391      // ceil(50000/128)
#define GRID_E 148
#define PASS_F4 (N_NODES * 32)      // nfeat passthrough in float4 units

// fp16 tile geometry: 128 rows x 128 cols, row stride 272B (136 halfs).
// 272/4 = 68 ≡ 4 (mod 32) => conflict-free for the mma fragment pattern with
// addresses LINEAR in k/mi/nt (LDS immediates).
#define RS16 272
#define T16_BYTES (128 * RS16)      // 34816
// fp32 staging tile for cp.async efeat prefetch. 528B rows (132 floats ≡ 4
// mod 32) so the residual LDS.128 reads are phase-conflict-free too.
#define RSTG 528
#define STG_BYTES (128 * RSTG)      // 67584

// Node projection scratch in FP16 (b1 folded into srcproj): 2 x 12.8MB ->
// both tables fully L2-resident, gathers are one LDG.128/row.
static __device__ uint16_t g_srcproj[(size_t)N_NODES * 128];
static __device__ uint16_t g_dstproj[(size_t)N_NODES * 128];

// ---------------- helpers ----------------

DEVINL uint32_t smem_u32(const void* p) {
    uint32_t a;
    asm("{ .reg .u64 t; cvta.to.shared.u64 t, %1; cvt.u32.u64 %0, t; }" : "=r"(a) : "l"(p));
    return a;
}
DEVINL uint32_t packh2(float lo, float hi) {
    uint32_t r;
    asm("cvt.rn.f16x2.f32 %0, %1, %2;" : "=r"(r) : "f"(hi), "f"(lo));
    return r;
}
DEVINL float2 h2f2(uint32_t h) {
    return __half22float2(*reinterpret_cast<const __half2*>(&h));
}
DEVINL uint32_t lds32(uint32_t a) {
    uint32_t v;
    asm volatile("ld.shared.b32 %0, [%1];" : "=r"(v) : "r"(a));
    return v;
}
DEVINL float4 lds128f(uint32_t a) {
    float4 v;
    asm volatile("ld.shared.v4.f32 {%0,%1,%2,%3}, [%4];"
                 : "=f"(v.x), "=f"(v.y), "=f"(v.z), "=f"(v.w) : "r"(a));
    return v;
}
DEVINL void sts64f(uint32_t a, float x, float y) {
    asm volatile("st.shared.v2.f32 [%0], {%1,%2};" :: "r"(a), "f"(x), "f"(y));
}
DEVINL void sts64(uint32_t a, uint32_t x, uint32_t y) {
    asm volatile("st.shared.v2.b32 [%0], {%1,%2};" :: "r"(a), "r"(x), "r"(y));
}
DEVINL void sts128(uint32_t a, uint32_t x, uint32_t y, uint32_t z, uint32_t w) {
    asm volatile("st.shared.v4.b32 [%0], {%1,%2,%3,%4};" :: "r"(a), "r"(x), "r"(y), "r"(z), "r"(w));
}
DEVINL void cpasync16(uint32_t s, const void* g, int srcbytes) {
    asm volatile("cp.async.cg.shared.global [%0], [%1], 16, %2;"
                 :: "r"(s), "l"(g), "r"(srcbytes));
}
DEVINL void cpcommit() { asm volatile("cp.async.commit_group;" ::: "memory"); }
DEVINL void cpwait0()  { asm volatile("cp.async.wait_group 0;" ::: "memory"); }

// mbarrier-based group sync (R11; avoids BAR hw which faulted in R9/R10).
DEVINL void mbar_init(uint32_t a, uint32_t cnt) {
    asm volatile("mbarrier.init.shared.b64 [%0], %1;" :: "r"(a), "r"(cnt) : "memory");
}
DEVINL void gsync(uint32_t mb, uint32_t ph) {
    asm volatile(
        "{\n\t.reg .pred P;\n\t"
        "mbarrier.arrive.shared.b64 _, [%0];\n\t"
        "LW%=:\n\t"
        "mbarrier.try_wait.parity.acquire.cta.shared::cta.b64 P, [%0], %1, 0x989680;\n\t"
        "@P bra.uni LD%=;\n\t"
        "bra.uni LW%=;\n\t"
        "LD%=:\n\t}"
        :: "r"(mb), "r"(ph) : "memory");
}

// silu(x) = x*sigmoid(x) = h + h*tanh(h), h = x/2  (1 MUFU)
DEVINL float silu_f(float x) {
    float h = 0.5f * x, t;
    asm("tanh.approx.f32 %0, %1;" : "=f"(t) : "f"(h));
    return fmaf(h, t, h);
}

// Out-dim permutation: thread's D-frag cols become CONTIGUOUS 32*cg+8*lm+{0..7}.
DEVINL int permn(int n) {
    return (n & 0x61) | ((n & 6) << 2) | ((n >> 2) & 6);
}

// fp16 tile address: row r, BYTE column cb.
DEVINL uint32_t adr16(uint32_t b, int r, int cb) {
    return b + (uint32_t)r * (uint32_t)RS16 + (uint32_t)cb;
}

// m16n8k16 fp16 HMMA, fp32 accum (base-target PTX, sm_80+)
DEVINL void mma16(float* d, const uint32_t* a, uint32_t b0, uint32_t b1) {
    asm volatile(
        "mma.sync.aligned.m16n8k16.row.col.f32.f16.f16.f32 "
        "{%0,%1,%2,%3}, {%4,%5,%6,%7}, {%8,%9}, {%0,%1,%2,%3};"
        : "+f"(d[0]), "+f"(d[1]), "+f"(d[2]), "+f"(d[3])
        : "r"(a[0]), "r"(a[1]), "r"(a[2]), "r"(a[3]), "r"(b0), "r"(b1));
}

// Load [128 out][128 in] row-major fp32 weight into fp16 SMEM (out-rows permuted).
DEVINL void load_weight16(uint32_t sbW, const float* __restrict__ W, int tid) {
#pragma unroll 1
    for (int i = tid; i < 4096; i += 512) {
        int n = i >> 5, k4 = (i & 31) << 2;
        float4 v = __ldg((const float4*)W + i);
        sts64(adr16(sbW, permn(n), k4 * 2), packh2(v.x, v.y), packh2(v.z, v.w));
    }
}

// 128x128x128 fp16 GEMM, 16 warps. Warp w: rg=w>>2 rows [32rg,+32), cg=w&3
// cols [32cg,+32). 8 k-steps of 16. acc[(mi*4+nt)*4 + 2*h + e] (fp32).
DEVINL void gemm16(uint32_t sbA, uint32_t sbW, int rg, int cg, int lq, int lm,
                   float acc[32]) {
    const uint32_t bA = sbA + (uint32_t)(32 * rg + lq) * RS16 + 4u * lm;
    const uint32_t bB = sbW + (uint32_t)(32 * cg + lq) * RS16 + 4u * lm;
#pragma unroll
    for (int kk = 0; kk < 8; kk++) {
        uint32_t a[2][4];
#pragma unroll
        for (int mi = 0; mi < 2; mi++) {
            const uint32_t r = bA + (uint32_t)(mi * 16 * RS16 + kk * 32);
            a[mi][0] = lds32(r);
            a[mi][1] = lds32(r + 8 * RS16);
            a[mi][2] = lds32(r + 16);
            a[mi][3] = lds32(r + 8 * RS16 + 16);
        }
#pragma unroll
        for (int nt = 0; nt < 4; nt++) {
            const uint32_t rb = bB + (uint32_t)(nt * 8 * RS16 + kk * 32);
            uint32_t b0 = lds32(rb);
            uint32_t b1 = lds32(rb + 16);
            mma16(acc + nt * 4,      a[0], b0, b1);
            mma16(acc + 16 + nt * 4, a[1], b0, b1);
        }
    }
}

#define ACCJ(mi, h, j) acc[((mi) * 4 + ((j) >> 1)) * 4 + 2 * (h) + ((j) & 1)]

// ---------------- node projection kernel ----------------
// SMEM: Ws16[0,34816) Wd16[34816,69632) A16[69632,104448) b1[104448,+512)
#define NODE_SMEM 104960

__global__ void __launch_bounds__(512, 1)
node_kernel(const float* __restrict__ nfeat, const float* __restrict__ Ws,
            const float* __restrict__ Wd, const float* __restrict__ b1) {
    extern __shared__ char smem[];
    const uint32_t sb = smem_u32(smem);
    const uint32_t sWS = sb, sWD = sb + T16_BYTES, sA = sb + 2 * T16_BYTES;
    const uint32_t sB1 = sb + 3 * T16_BYTES;
    const int tid = threadIdx.x, w = tid >> 5, lane = tid & 31;
    const int lq = lane >> 2, lm = lane & 3, rg = w >> 2, cg = w & 3;

    load_weight16(sWS, Ws, tid);
    load_weight16(sWD, Wd, tid);
    if (tid < 128) ((float*)(smem + 3 * T16_BYTES))[tid] = __ldg(b1 + tid);

    const int base = blockIdx.x * 128;
#pragma unroll
    for (int i = 0; i < 8; i++) {
        const int f4 = tid + 512 * i;
        const int row = f4 >> 5, c4 = f4 & 31;
        const int ng = base + row;
        const bool v = ng < N_NODES;
        float4 x = v ? __ldg((const float4*)(nfeat + (size_t)ng * 128) + c4)
                     : make_float4(0.f, 0.f, 0.f, 0.f);
        sts64(adr16(sA, row, c4 * 8), packh2(x.x, x.y), packh2(x.z, x.w));
    }
    __syncthreads();

    const int Lb = 32 * cg + 8 * lm;                 // thread's logical col base
    const float4 bb0 = lds128f(sB1 + (uint32_t)Lb * 4);
    const float4 bb1 = lds128f(sB1 + (uint32_t)Lb * 4 + 16);

    float acc[32];
#pragma unroll
    for (int i = 0; i < 32; i++) acc[i] = 0.f;
    gemm16(sA, sWS, rg, cg, lq, lm, acc);
#pragma unroll
    for (int mi = 0; mi < 2; mi++)
#pragma unroll
    for (int h = 0; h < 2; h++) {
        const int ng = base + 32 * rg + 16 * mi + 8 * h + lq;
        if (ng < N_NODES) {
            uint4 o;
            o.x = packh2(ACCJ(mi, h, 0) + bb0.x, ACCJ(mi, h, 1) + bb0.y);
            o.y = packh2(ACCJ(mi, h, 2) + bb0.z, ACCJ(mi, h, 3) + bb0.w);
            o.z = packh2(ACCJ(mi, h, 4) + bb1.x, ACCJ(mi, h, 5) + bb1.y);
            o.w = packh2(ACCJ(mi, h, 6) + bb1.z, ACCJ(mi, h, 7) + bb1.w);
            *(uint4*)(g_srcproj + (size_t)ng * 128 + Lb) = o;
        }
    }

#pragma unroll
    for (int i = 0; i < 32; i++) acc[i] = 0.f;
    gemm16(sA, sWD, rg, cg, lq, lm, acc);
#pragma unroll
    for (int mi = 0; mi < 2; mi++)
#pragma unroll
    for (int h = 0; h < 2; h++) {
        const int ng = base + 32 * rg + 16 * mi + 8 * h + lq;
        if (ng < N_NODES) {
            uint4 o;
            o.x = packh2(ACCJ(mi, h, 0), ACCJ(mi, h, 1));
            o.y = packh2(ACCJ(mi, h, 2), ACCJ(mi, h, 3));
            o.z = packh2(ACCJ(mi, h, 4), ACCJ(mi, h, 5));
            o.w = packh2(ACCJ(mi, h, 6), ACCJ(mi, h, 7));
            *(uint4*)(g_dstproj + (size_t)ng * 128 + Lb) = o;
        }
    }
}

// ---------------- fused edge kernel (persistent, 512 thr) ----------------
// SMEM: We16[0,34816) Wo16[34816,69632) A16[69632,104448) STG[104448,172032)
//       LN[172032,+4096) bo@176128 gamma@176640 beta@177152 mbar@177664(+128)
#define EDGE_SMEM 177792

// Group-local prefetch of NEXT tile's efeat (raw fp32) into the staging buffer.
DEVINL void prefetch_efeat_grp(uint32_t sSTG, const float* __restrict__ efeat,
                               int tile, int rg, int gt) {
    const int base = tile * 128 + 32 * rg;
#pragma unroll
    for (int i = 0; i < 8; i++) {
        const int f4 = gt + 128 * i;
        const int row = f4 >> 5, c4 = f4 & 31;
        const int e = base + row;
        const bool v = e < N_EDGES;
        const float* g = efeat + (size_t)(v ? e : 0) * 128 + c4 * 4;
        cpasync16(sSTG + (uint32_t)(32 * rg + row) * RSTG + (uint32_t)c4 * 16u,
                  g, v ? 16 : 0);
    }
    cpcommit();
}

// Convert this thread's own staged fp32 bytes -> fp16 A tile.
DEVINL void convert_rows(uint32_t sA16, uint32_t sSTG, int rg, int gt) {
#pragma unroll
    for (int i = 0; i < 8; i++) {
        const int f4 = gt + 128 * i;
        const int row = 32 * rg + (f4 >> 5), c4 = f4 & 31;
        float4 v = lds128f(sSTG + (uint32_t)row * RSTG + (uint32_t)c4 * 16u);
        sts64(adr16(sA16, row, c4 * 8), packh2(v.x, v.y), packh2(v.z, v.w));
    }
}

__global__ void __launch_bounds__(512, 1)
edge_kernel(const float* __restrict__ efeat, const int* __restrict__ src,
            const int* __restrict__ dst, const float* __restrict__ We,
            const float* __restrict__ Wo, const float* __restrict__ bo,
            const float* __restrict__ gamma, const float* __restrict__ beta,
            const float* __restrict__ nfeat, float* __restrict__ nfeat_out,
            float* __restrict__ out) {
    extern __shared__ char smem[];
    const uint32_t sb = smem_u32(smem);
    const uint32_t sWE = sb, sWO = sb + T16_BYTES, sA16 = sb + 2 * T16_BYTES;
    const uint32_t sSTG = sb + 3 * T16_BYTES;
    const uint32_t sLN = sSTG + STG_BYTES;
    const uint32_t sBO = sLN + 4096, sGA = sBO + 512, sBE = sGA + 512;
    const uint32_t sMB = sBE + 512;                  // 16 mbarriers
    const int tid = threadIdx.x, w = tid >> 5, lane = tid & 31;
    const int lq = lane >> 2, lm = lane & 3, rg = w >> 2, cg = w & 3;
    const int gt = tid & 127;
    const uint32_t mb0 = sMB + (uint32_t)rg * 32u;

    load_weight16(sWE, We, tid);
    load_weight16(sWO, Wo, tid);
    if (tid < 128) {
        ((float*)(smem + (sBO - sb)))[tid] = __ldg(bo + tid);
        ((float*)(smem + (sGA - sb)))[tid] = __ldg(gamma + tid);
        ((float*)(smem + (sBE - sb)))[tid] = __ldg(beta + tid);
    }
    if (tid < 16) mbar_init(sMB + (uint32_t)tid * 8u, 128);
    prefetch_efeat_grp(sSTG, efeat, blockIdx.x, rg, gt);
    __syncthreads();      // weights/biases/mbarriers visible; groups decouple after

    const int Lb = 32 * cg + 8 * lm;
    const float4 bo0 = lds128f(sBO + (uint32_t)Lb * 4);
    const float4 bo1 = lds128f(sBO + (uint32_t)Lb * 4 + 16);
    const float4 ga0 = lds128f(sGA + (uint32_t)Lb * 4);
    const float4 ga1 = lds128f(sGA + (uint32_t)Lb * 4 + 16);
    const float4 be0 = lds128f(sBE + (uint32_t)Lb * 4);
    const float4 be1 = lds128f(sBE + (uint32_t)Lb * 4 + 16);

    uint32_t ph = 0;

    for (int tile = blockIdx.x; tile < ETILES; tile += GRID_E) {
        const int base = tile * 128;
        cpwait0();
        convert_rows(sA16, sSTG, rg, gt);     // staged fp32 -> fp16 A tile
        gsync(mb0 + 0, ph);                   // (a) group's 32 A16 rows ready

        // Indices + all gather loads now (latency hides under GEMM1).
        bool vr[4];
        uint4 sg[4], dg[4];
#pragma unroll
        for (int mi = 0; mi < 2; mi++)
#pragma unroll
        for (int h = 0; h < 2; h++) {
            const int e = base + 32 * rg + 16 * mi + 8 * h + lq;
            const bool v = e < N_EDGES;
            vr[mi * 2 + h] = v;
            const int si = v ? __ldg(src + e) : 0;
            const int di = v ? __ldg(dst + e) : 0;
            sg[mi * 2 + h] = __ldg((const uint4*)(g_srcproj + (size_t)si * 128 + Lb));
            dg[mi * 2 + h] = __ldg((const uint4*)(g_dstproj + (size_t)di * 128 + Lb));
        }

        // nfeat passthrough slice (pure copy; latency hidden under GEMM1+epi1)
        const int cidx = tile * 512 + tid;
        const bool cvalid = cidx < PASS_F4;
        float4 cpy = make_float4(0.f, 0.f, 0.f, 0.f);
        if (cvalid) cpy = __ldg((const float4*)nfeat + cidx);

        float acc[32];
#pragma unroll
        for (int i = 0; i < 32; i++) acc[i] = 0.f;
        gemm16(sA16, sWE, rg, cg, lq, lm, acc);   // h-pre = efeat @ We^T
        gsync(mb0 + 8, ph);                   // (c) group done reading its A rows

        // epilogue1: + srcproj (b1 folded) + dstproj, SiLU, act -> A16
#pragma unroll
        for (int mi = 0; mi < 2; mi++)
#pragma unroll
        for (int h = 0; h < 2; h++) {
            const int R = 32 * rg + 16 * mi + 8 * h + lq;
            const uint4 sv = sg[mi * 2 + h], dv = dg[mi * 2 + h];
            float2 s0 = h2f2(sv.x), s1 = h2f2(sv.y), s2 = h2f2(sv.z), s3 = h2f2(sv.w);
            float2 d0 = h2f2(dv.x), d1 = h2f2(dv.y), d2 = h2f2(dv.z), d3 = h2f2(dv.w);
            float x0 = silu_f(ACCJ(mi, h, 0) + s0.x + d0.x);
            float x1 = silu_f(ACCJ(mi, h, 1) + s0.y + d0.y);
            float x2 = silu_f(ACCJ(mi, h, 2) + s1.x + d1.x);
            float x3 = silu_f(ACCJ(mi, h, 3) + s1.y + d1.y);
            float x4 = silu_f(ACCJ(mi, h, 4) + s2.x + d2.x);
            float x5 = silu_f(ACCJ(mi, h, 5) + s2.y + d2.y);
            float x6 = silu_f(ACCJ(mi, h, 6) + s3.x + d3.x);
            float x7 = silu_f(ACCJ(mi, h, 7) + s3.y + d3.y);
            sts128(adr16(sA16, R, Lb * 2),
                   packh2(x0, x1), packh2(x2, x3), packh2(x4, x5), packh2(x6, x7));
        }
        gsync(mb0 + 16, ph);                  // (d) group's act rows complete

#pragma unroll
        for (int i = 0; i < 32; i++) acc[i] = 0.f;
        gemm16(sA16, sWO, rg, cg, lq, lm, acc);   // o-pre = act @ Wo^T

        // Residual efeat from the STAGING buffer (exact fp32 bits, no global
        // re-read). Must complete before gsync(e): after that barrier another
        // group thread's prefetch may overwrite these rows.
        float4 res[8];
#pragma unroll
        for (int mi = 0; mi < 2; mi++)
#pragma unroll
        for (int h = 0; h < 2; h++) {
            const int R = 32 * rg + 16 * mi + 8 * h + lq;
            const uint32_t ra = sSTG + (uint32_t)R * RSTG + (uint32_t)Lb * 4u;
            res[(mi * 2 + h) * 2]     = lds128f(ra);
            res[(mi * 2 + h) * 2 + 1] = lds128f(ra + 16);
        }

        // epilogue2a: + bo, LayerNorm partials
#pragma unroll
        for (int mi = 0; mi < 2; mi++)
#pragma unroll
        for (int h = 0; h < 2; h++) {
            float s = 0.f, q = 0.f;
#pragma unroll
            for (int j = 0; j < 8; j++) {
                const float b = (j < 4) ? ((const float*)&bo0)[j] : ((const float*)&bo1)[j - 4];
                float x = ACCJ(mi, h, j) + b;
                ACCJ(mi, h, j) = x;
                s += x;
                q += x * x;
            }
            s += __shfl_xor_sync(0xffffffffu, s, 1);
            q += __shfl_xor_sync(0xffffffffu, q, 1);
            s += __shfl_xor_sync(0xffffffffu, s, 2);
            q += __shfl_xor_sync(0xffffffffu, q, 2);
            if (lm == 0) {
                const int R = 32 * rg + 16 * mi + 8 * h + lq;
                sts64f(sLN + (uint32_t)(cg * 128 + R) * 8, s, q);
            }
        }
        gsync(mb0 + 24, ph);                  // (e) LN partials visible; STG free

        // prefetch next tile's efeat into staging (overlaps epilogue2b)
        if (tile + GRID_E < ETILES)
            prefetch_efeat_grp(sSTG, efeat, tile + GRID_E, rg, gt);

        // epilogue2b: normalize, affine, + residual (regs), store
#pragma unroll
        for (int mi = 0; mi < 2; mi++)
#pragma unroll
        for (int h = 0; h < 2; h++) {
            const int R = 32 * rg + 16 * mi + 8 * h + lq;
            const int e = base + R;
            const bool v = vr[mi * 2 + h];
            float2 p0 = *(float2*)(smem + (sLN - sb) + (uint32_t)R * 8);
            float2 p1 = *(float2*)(smem + (sLN - sb) + (uint32_t)(128 + R) * 8);
            float2 p2 = *(float2*)(smem + (sLN - sb) + (uint32_t)(256 + R) * 8);
            float2 p3 = *(float2*)(smem + (sLN - sb) + (uint32_t)(384 + R) * 8);
            const float mu  = (p0.x + p1.x + p2.x + p3.x) * 0.0078125f;
            const float var = (p0.y + p1.y + p2.y + p3.y) * 0.0078125f - mu * mu;
            const float rs  = rsqrtf(var + 1e-5f);
            const float4 r0 = res[(mi * 2 + h) * 2];
            const float4 r1 = res[(mi * 2 + h) * 2 + 1];
            float4 o0, o1;
            o0.x = (ACCJ(mi, h, 0) - mu) * rs * ga0.x + be0.x + r0.x;
            o0.y = (ACCJ(mi, h, 1) - mu) * rs * ga0.y + be0.y + r0.y;
            o0.z = (ACCJ(mi, h, 2) - mu) * rs * ga0.z + be0.z + r0.z;
            o0.w = (ACCJ(mi, h, 3) - mu) * rs * ga0.w + be0.w + r0.w;
            o1.x = (ACCJ(mi, h, 4) - mu) * rs * ga1.x + be1.x + r1.x;
            o1.y = (ACCJ(mi, h, 5) - mu) * rs * ga1.y + be1.y + r1.y;
            o1.z = (ACCJ(mi, h, 6) - mu) * rs * ga1.z + be1.z + r1.z;
            o1.w = (ACCJ(mi, h, 7) - mu) * rs * ga1.w + be1.w + r1.w;
            if (v) {
                float4* po = (float4*)(out + (size_t)e * 128 + Lb);
                po[0] = o0; po[1] = o1;
            }
        }

        // complete the nfeat passthrough slice
        if (cvalid) ((float4*)nfeat_out)[cidx] = cpy;

        ph ^= 1;
    }
}

// ---------------- launch ----------------

extern "C" void kernel_launch(void* const* d_in, const int* in_sizes, int n_in,
                              void* d_out, int out_size) {
    const float* efeat = (const float*)d_in[0];
    const float* nfeat = (const float*)d_in[1];
    const int*   src   = (const int*)d_in[2];
    const int*   dst   = (const int*)d_in[3];
    const float* We    = (const float*)d_in[4];
    const float* Ws    = (const float*)d_in[5];
    const float* Wd    = (const float*)d_in[6];
    const float* b1    = (const float*)d_in[7];
    const float* Wo    = (const float*)d_in[8];
    const float* bo    = (const float*)d_in[9];
    const float* gamma = (const float*)d_in[10];
    const float* beta  = (const float*)d_in[11];
    float* out = (float*)d_out;

    cudaFuncSetAttribute(node_kernel, cudaFuncAttributeMaxDynamicSharedMemorySize, NODE_SMEM);
    cudaFuncSetAttribute(edge_kernel, cudaFuncAttributeMaxDynamicSharedMemorySize, EDGE_SMEM);

    node_kernel<<<NTILES, 512, NODE_SMEM>>>(nfeat, Ws, Wd, b1);
    edge_kernel<<<GRID_E, 512, EDGE_SMEM>>>(efeat, src, dst, We, Wo, bo, gamma, beta,
                                            nfeat, out + (size_t)N_EDGES * 128, out);
}

// round 15
// speedup vs baseline: 1.0239x; 1.0239x over previous
#include <cuda_runtime.h>
#include <cuda_fp16.h>
#include <cstdint>

#define DEVINL static __device__ __forceinline__

#define N_EDGES 600000
#define N_NODES 50000
#define ETILES 4688     // ceil(600000/128)
#define NTILES 391      // ceil(50000/128)
#define GRID_E 148
#define PASS_F4 (N_NODES * 32)      // nfeat passthrough in float4 units

// fp16 tile geometry: 128 rows x 128 cols, row stride 272B (136 halfs).
// 272/4 = 68 ≡ 4 (mod 32) => conflict-free for the mma fragment pattern with
// addresses LINEAR in k/mi/nt (LDS immediates).
#define RS16 272
#define T16_BYTES (128 * RS16)      // 34816
// fp32 staging tile for cp.async efeat prefetch (plain 512B rows).
#define RSTG 512
#define STG_BYTES (128 * RSTG)      // 65536

// Node projection scratch in FP16 (b1 folded into srcproj): 2 x 12.8MB ->
// both tables fully L2-resident, gathers are one LDG.128/row.
static __device__ uint16_t g_srcproj[(size_t)N_NODES * 128];
static __device__ uint16_t g_dstproj[(size_t)N_NODES * 128];

// ---------------- helpers ----------------

DEVINL uint32_t smem_u32(const void* p) {
    uint32_t a;
    asm("{ .reg .u64 t; cvta.to.shared.u64 t, %1; cvt.u32.u64 %0, t; }" : "=r"(a) : "l"(p));
    return a;
}
DEVINL uint32_t packh2(float lo, float hi) {
    uint32_t r;
    asm("cvt.rn.f16x2.f32 %0, %1, %2;" : "=r"(r) : "f"(hi), "f"(lo));
    return r;
}
DEVINL float2 h2f2(uint32_t h) {
    return __half22float2(*reinterpret_cast<const __half2*>(&h));
}
DEVINL uint32_t lds32(uint32_t a) {
    uint32_t v;
    asm volatile("ld.shared.b32 %0, [%1];" : "=r"(v) : "r"(a));
    return v;
}
DEVINL float4 lds128f(uint32_t a) {
    float4 v;
    asm volatile("ld.shared.v4.f32 {%0,%1,%2,%3}, [%4];"
                 : "=f"(v.x), "=f"(v.y), "=f"(v.z), "=f"(v.w) : "r"(a));
    return v;
}
DEVINL void sts64f(uint32_t a, float x, float y) {
    asm volatile("st.shared.v2.f32 [%0], {%1,%2};" :: "r"(a), "f"(x), "f"(y));
}
DEVINL void sts64(uint32_t a, uint32_t x, uint32_t y) {
    asm volatile("st.shared.v2.b32 [%0], {%1,%2};" :: "r"(a), "r"(x), "r"(y));
}
DEVINL void sts128(uint32_t a, uint32_t x, uint32_t y, uint32_t z, uint32_t w) {
    asm volatile("st.shared.v4.b32 [%0], {%1,%2,%3,%4};" :: "r"(a), "r"(x), "r"(y), "r"(z), "r"(w));
}
DEVINL void cpasync16(uint32_t s, const void* g, int srcbytes) {
    asm volatile("cp.async.cg.shared.global [%0], [%1], 16, %2;"
                 :: "r"(s), "l"(g), "r"(srcbytes));
}
DEVINL void cpcommit() { asm volatile("cp.async.commit_group;" ::: "memory"); }
DEVINL void cpwait0()  { asm volatile("cp.async.wait_group 0;" ::: "memory"); }

// mbarrier-based group sync (R11; avoids BAR hw which faulted in R9/R10).
DEVINL void mbar_init(uint32_t a, uint32_t cnt) {
    asm volatile("mbarrier.init.shared.b64 [%0], %1;" :: "r"(a), "r"(cnt) : "memory");
}
DEVINL void gsync(uint32_t mb, uint32_t ph) {
    asm volatile(
        "{\n\t.reg .pred P;\n\t"
        "mbarrier.arrive.shared.b64 _, [%0];\n\t"
        "LW%=:\n\t"
        "mbarrier.try_wait.parity.acquire.cta.shared::cta.b64 P, [%0], %1, 0x989680;\n\t"
        "@P bra.uni LD%=;\n\t"
        "bra.uni LW%=;\n\t"
        "LD%=:\n\t}"
        :: "r"(mb), "r"(ph) : "memory");
}

// silu(x) = x*sigmoid(x) = h + h*tanh(h), h = x/2  (1 MUFU)
DEVINL float silu_f(float x) {
    float h = 0.5f * x, t;
    asm("tanh.approx.f32 %0, %1;" : "=f"(t) : "f"(h));
    return fmaf(h, t, h);
}

// Out-dim permutation: thread's D-frag cols become CONTIGUOUS 32*cg+8*lm+{0..7}.
DEVINL int permn(int n) {
    return (n & 0x61) | ((n & 6) << 2) | ((n >> 2) & 6);
}

// fp16 tile address: row r, BYTE column cb.
DEVINL uint32_t adr16(uint32_t b, int r, int cb) {
    return b + (uint32_t)r * (uint32_t)RS16 + (uint32_t)cb;
}

// m16n8k16 fp16 HMMA, fp32 accum (base-target PTX, sm_80+)
DEVINL void mma16(float* d, const uint32_t* a, uint32_t b0, uint32_t b1) {
    asm volatile(
        "mma.sync.aligned.m16n8k16.row.col.f32.f16.f16.f32 "
        "{%0,%1,%2,%3}, {%4,%5,%6,%7}, {%8,%9}, {%0,%1,%2,%3};"
        : "+f"(d[0]), "+f"(d[1]), "+f"(d[2]), "+f"(d[3])
        : "r"(a[0]), "r"(a[1]), "r"(a[2]), "r"(a[3]), "r"(b0), "r"(b1));
}

// Load [128 out][128 in] row-major fp32 weight into fp16 SMEM (out-rows permuted).
DEVINL void load_weight16(uint32_t sbW, const float* __restrict__ W, int tid) {
#pragma unroll 1
    for (int i = tid; i < 4096; i += 512) {
        int n = i >> 5, k4 = (i & 31) << 2;
        float4 v = __ldg((const float4*)W + i);
        sts64(adr16(sbW, permn(n), k4 * 2), packh2(v.x, v.y), packh2(v.z, v.w));
    }
}

// 128x128x128 fp16 GEMM, 16 warps. Warp w: rg=w>>2 rows [32rg,+32), cg=w&3
// cols [32cg,+32). 8 k-steps of 16. acc[(mi*4+nt)*4 + 2*h + e] (fp32).
DEVINL void gemm16(uint32_t sbA, uint32_t sbW, int rg, int cg, int lq, int lm,
                   float acc[32]) {
    const uint32_t bA = sbA + (uint32_t)(32 * rg + lq) * RS16 + 4u * lm;
    const uint32_t bB = sbW + (uint32_t)(32 * cg + lq) * RS16 + 4u * lm;
#pragma unroll
    for (int kk = 0; kk < 8; kk++) {
        uint32_t a[2][4];
#pragma unroll
        for (int mi = 0; mi < 2; mi++) {
            const uint32_t r = bA + (uint32_t)(mi * 16 * RS16 + kk * 32);
            a[mi][0] = lds32(r);
            a[mi][1] = lds32(r + 8 * RS16);
            a[mi][2] = lds32(r + 16);
            a[mi][3] = lds32(r + 8 * RS16 + 16);
        }
#pragma unroll
        for (int nt = 0; nt < 4; nt++) {
            const uint32_t rb = bB + (uint32_t)(nt * 8 * RS16 + kk * 32);
            uint32_t b0 = lds32(rb);
            uint32_t b1 = lds32(rb + 16);
            mma16(acc + nt * 4,      a[0], b0, b1);
            mma16(acc + 16 + nt * 4, a[1], b0, b1);
        }
    }
}

#define ACCJ(mi, h, j) acc[((mi) * 4 + ((j) >> 1)) * 4 + 2 * (h) + ((j) & 1)]

// ---------------- node projection kernel ----------------
// SMEM: Ws16[0,34816) Wd16[34816,69632) A16[69632,104448) b1[104448,+512)
#define NODE_SMEM 104960

__global__ void __launch_bounds__(512, 1)
node_kernel(const float* __restrict__ nfeat, const float* __restrict__ Ws,
            const float* __restrict__ Wd, const float* __restrict__ b1) {
    extern __shared__ char smem[];
    const uint32_t sb = smem_u32(smem);
    const uint32_t sWS = sb, sWD = sb + T16_BYTES, sA = sb + 2 * T16_BYTES;
    const uint32_t sB1 = sb + 3 * T16_BYTES;
    const int tid = threadIdx.x, w = tid >> 5, lane = tid & 31;
    const int lq = lane >> 2, lm = lane & 3, rg = w >> 2, cg = w & 3;

    load_weight16(sWS, Ws, tid);
    load_weight16(sWD, Wd, tid);
    if (tid < 128) ((float*)(smem + 3 * T16_BYTES))[tid] = __ldg(b1 + tid);

    const int base = blockIdx.x * 128;
#pragma unroll
    for (int i = 0; i < 8; i++) {
        const int f4 = tid + 512 * i;
        const int row = f4 >> 5, c4 = f4 & 31;
        const int ng = base + row;
        const bool v = ng < N_NODES;
        float4 x = v ? __ldg((const float4*)(nfeat + (size_t)ng * 128) + c4)
                     : make_float4(0.f, 0.f, 0.f, 0.f);
        sts64(adr16(sA, row, c4 * 8), packh2(x.x, x.y), packh2(x.z, x.w));
    }
    __syncthreads();

    const int Lb = 32 * cg + 8 * lm;                 // thread's logical col base
    const float4 bb0 = lds128f(sB1 + (uint32_t)Lb * 4);
    const float4 bb1 = lds128f(sB1 + (uint32_t)Lb * 4 + 16);

    float acc[32];
#pragma unroll
    for (int i = 0; i < 32; i++) acc[i] = 0.f;
    gemm16(sA, sWS, rg, cg, lq, lm, acc);
#pragma unroll
    for (int mi = 0; mi < 2; mi++)
#pragma unroll
    for (int h = 0; h < 2; h++) {
        const int ng = base + 32 * rg + 16 * mi + 8 * h + lq;
        if (ng < N_NODES) {
            uint4 o;
            o.x = packh2(ACCJ(mi, h, 0) + bb0.x, ACCJ(mi, h, 1) + bb0.y);
            o.y = packh2(ACCJ(mi, h, 2) + bb0.z, ACCJ(mi, h, 3) + bb0.w);
            o.z = packh2(ACCJ(mi, h, 4) + bb1.x, ACCJ(mi, h, 5) + bb1.y);
            o.w = packh2(ACCJ(mi, h, 6) + bb1.z, ACCJ(mi, h, 7) + bb1.w);
            *(uint4*)(g_srcproj + (size_t)ng * 128 + Lb) = o;
        }
    }

#pragma unroll
    for (int i = 0; i < 32; i++) acc[i] = 0.f;
    gemm16(sA, sWD, rg, cg, lq, lm, acc);
#pragma unroll
    for (int mi = 0; mi < 2; mi++)
#pragma unroll
    for (int h = 0; h < 2; h++) {
        const int ng = base + 32 * rg + 16 * mi + 8 * h + lq;
        if (ng < N_NODES) {
            uint4 o;
            o.x = packh2(ACCJ(mi, h, 0), ACCJ(mi, h, 1));
            o.y = packh2(ACCJ(mi, h, 2), ACCJ(mi, h, 3));
            o.z = packh2(ACCJ(mi, h, 4), ACCJ(mi, h, 5));
            o.w = packh2(ACCJ(mi, h, 6), ACCJ(mi, h, 7));
            *(uint4*)(g_dstproj + (size_t)ng * 128 + Lb) = o;
        }
    }
}

// ---------------- fused edge kernel (persistent, 512 thr) ----------------
// SMEM: We16[0,34816) Wo16[34816,69632) A16[69632,104448) STG[104448,169984)
//       LN[169984,+4096) bo@174080 gamma@174592 beta@175104 mbar@175616(+128)
#define EDGE_SMEM 175744

// Group-local prefetch of NEXT tile's efeat (raw fp32) into the staging buffer.
DEVINL void prefetch_efeat_grp(uint32_t sSTG, const float* __restrict__ efeat,
                               int tile, int rg, int gt) {
    const int base = tile * 128 + 32 * rg;
#pragma unroll
    for (int i = 0; i < 8; i++) {
        const int f4 = gt + 128 * i;
        const int row = f4 >> 5, c4 = f4 & 31;
        const int e = base + row;
        const bool v = e < N_EDGES;
        const float* g = efeat + (size_t)(v ? e : 0) * 128 + c4 * 4;
        cpasync16(sSTG + (uint32_t)(32 * rg + row) * RSTG + (uint32_t)c4 * 16u,
                  g, v ? 16 : 0);
    }
    cpcommit();
}

// Convert this thread's own staged fp32 bytes -> fp16 A tile.
DEVINL void convert_rows(uint32_t sA16, uint32_t sSTG, int rg, int gt) {
#pragma unroll
    for (int i = 0; i < 8; i++) {
        const int f4 = gt + 128 * i;
        const int row = 32 * rg + (f4 >> 5), c4 = f4 & 31;
        float4 v = lds128f(sSTG + (uint32_t)row * RSTG + (uint32_t)c4 * 16u);
        sts64(adr16(sA16, row, c4 * 8), packh2(v.x, v.y), packh2(v.z, v.w));
    }
}

__global__ void __launch_bounds__(512, 1)
edge_kernel(const float* __restrict__ efeat, const int* __restrict__ src,
            const int* __restrict__ dst, const float* __restrict__ We,
            const float* __restrict__ Wo, const float* __restrict__ bo,
            const float* __restrict__ gamma, const float* __restrict__ beta,
            const float* __restrict__ nfeat, float* __restrict__ nfeat_out,
            float* __restrict__ out) {
    extern __shared__ char smem[];
    const uint32_t sb = smem_u32(smem);
    const uint32_t sWE = sb, sWO = sb + T16_BYTES, sA16 = sb + 2 * T16_BYTES;
    const uint32_t sSTG = sb + 3 * T16_BYTES;
    const uint32_t sLN = sSTG + STG_BYTES;
    const uint32_t sBO = sLN + 4096, sGA = sBO + 512, sBE = sGA + 512;
    const uint32_t sMB = sBE + 512;                  // 16 mbarriers
    const int tid = threadIdx.x, w = tid >> 5, lane = tid & 31;
    const int lq = lane >> 2, lm = lane & 3, rg = w >> 2, cg = w & 3;
    const int gt = tid & 127;
    const uint32_t mb0 = sMB + (uint32_t)rg * 32u;

    load_weight16(sWE, We, tid);
    load_weight16(sWO, Wo, tid);
    if (tid < 128) {
        ((float*)(smem + (sBO - sb)))[tid] = __ldg(bo + tid);
        ((float*)(smem + (sGA - sb)))[tid] = __ldg(gamma + tid);
        ((float*)(smem + (sBE - sb)))[tid] = __ldg(beta + tid);
    }
    if (tid < 16) mbar_init(sMB + (uint32_t)tid * 8u, 128);
    prefetch_efeat_grp(sSTG, efeat, blockIdx.x, rg, gt);
    __syncthreads();      // weights/biases/mbarriers visible; groups decouple after

    const int Lb = 32 * cg + 8 * lm;
    const float4 bo0 = lds128f(sBO + (uint32_t)Lb * 4);
    const float4 bo1 = lds128f(sBO + (uint32_t)Lb * 4 + 16);
    const float4 ga0 = lds128f(sGA + (uint32_t)Lb * 4);
    const float4 ga1 = lds128f(sGA + (uint32_t)Lb * 4 + 16);
    const float4 be0 = lds128f(sBE + (uint32_t)Lb * 4);
    const float4 be1 = lds128f(sBE + (uint32_t)Lb * 4 + 16);

    uint32_t ph = 0;

    for (int tile = blockIdx.x; tile < ETILES; tile += GRID_E) {
        const int base = tile * 128;
        cpwait0();
        convert_rows(sA16, sSTG, rg, gt);     // staged fp32 -> fp16 A tile
        gsync(mb0 + 0, ph);                   // (a) group's 32 A16 rows ready

        // Indices + all gather loads now (latency hides under GEMM1).
        bool vr[4];
        uint4 sg[4], dg[4];
#pragma unroll
        for (int mi = 0; mi < 2; mi++)
#pragma unroll
        for (int h = 0; h < 2; h++) {
            const int e = base + 32 * rg + 16 * mi + 8 * h + lq;
            const bool v = e < N_EDGES;
            vr[mi * 2 + h] = v;
            const int si = v ? __ldg(src + e) : 0;
            const int di = v ? __ldg(dst + e) : 0;
            sg[mi * 2 + h] = __ldg((const uint4*)(g_srcproj + (size_t)si * 128 + Lb));
            dg[mi * 2 + h] = __ldg((const uint4*)(g_dstproj + (size_t)di * 128 + Lb));
        }

        float acc[32];
#pragma unroll
        for (int i = 0; i < 32; i++) acc[i] = 0.f;
        gemm16(sA16, sWE, rg, cg, lq, lm, acc);   // h-pre = efeat @ We^T
        gsync(mb0 + 8, ph);                   // (c) group done reading its A rows

        // epilogue1: + srcproj (b1 folded) + dstproj, SiLU, act -> A16
#pragma unroll
        for (int mi = 0; mi < 2; mi++)
#pragma unroll
        for (int h = 0; h < 2; h++) {
            const int R = 32 * rg + 16 * mi + 8 * h + lq;
            const uint4 sv = sg[mi * 2 + h], dv = dg[mi * 2 + h];
            float2 s0 = h2f2(sv.x), s1 = h2f2(sv.y), s2 = h2f2(sv.z), s3 = h2f2(sv.w);
            float2 d0 = h2f2(dv.x), d1 = h2f2(dv.y), d2 = h2f2(dv.z), d3 = h2f2(dv.w);
            float x0 = silu_f(ACCJ(mi, h, 0) + s0.x + d0.x);
            float x1 = silu_f(ACCJ(mi, h, 1) + s0.y + d0.y);
            float x2 = silu_f(ACCJ(mi, h, 2) + s1.x + d1.x);
            float x3 = silu_f(ACCJ(mi, h, 3) + s1.y + d1.y);
            float x4 = silu_f(ACCJ(mi, h, 4) + s2.x + d2.x);
            float x5 = silu_f(ACCJ(mi, h, 5) + s2.y + d2.y);
            float x6 = silu_f(ACCJ(mi, h, 6) + s3.x + d3.x);
            float x7 = silu_f(ACCJ(mi, h, 7) + s3.y + d3.y);
            sts128(adr16(sA16, R, Lb * 2),
                   packh2(x0, x1), packh2(x2, x3), packh2(x4, x5), packh2(x6, x7));
        }
        gsync(mb0 + 16, ph);                  // (d) group's act rows complete

        // nfeat passthrough slice: load here (short live range; latency hides
        // under GEMM2 + epilogue2), store at loop end.
        const int cidx = tile * 512 + tid;
        const bool cvalid = cidx < PASS_F4;
        float4 cpy = make_float4(0.f, 0.f, 0.f, 0.f);
        if (cvalid) cpy = __ldg((const float4*)nfeat + cidx);

#pragma unroll
        for (int i = 0; i < 32; i++) acc[i] = 0.f;
        gemm16(sA16, sWO, rg, cg, lq, lm, acc);   // o-pre = act @ Wo^T

        // epilogue2a: + bo, LayerNorm partials
#pragma unroll
        for (int mi = 0; mi < 2; mi++)
#pragma unroll
        for (int h = 0; h < 2; h++) {
            float s = 0.f, q = 0.f;
#pragma unroll
            for (int j = 0; j < 8; j++) {
                const float b = (j < 4) ? ((const float*)&bo0)[j] : ((const float*)&bo1)[j - 4];
                float x = ACCJ(mi, h, j) + b;
                ACCJ(mi, h, j) = x;
                s += x;
                q += x * x;
            }
            s += __shfl_xor_sync(0xffffffffu, s, 1);
            q += __shfl_xor_sync(0xffffffffu, q, 1);
            s += __shfl_xor_sync(0xffffffffu, s, 2);
            q += __shfl_xor_sync(0xffffffffu, q, 2);
            if (lm == 0) {
                const int R = 32 * rg + 16 * mi + 8 * h + lq;
                sts64f(sLN + (uint32_t)(cg * 128 + R) * 8, s, q);
            }
        }
        gsync(mb0 + 24, ph);                  // (e) LN partials visible; STG free

        // prefetch next tile's efeat into staging (overlaps epilogue2b)
        if (tile + GRID_E < ETILES)
            prefetch_efeat_grp(sSTG, efeat, tile + GRID_E, rg, gt);

        // epilogue2b: normalize, affine, + residual efeat (L2-hot), store
#pragma unroll
        for (int mi = 0; mi < 2; mi++)
#pragma unroll
        for (int h = 0; h < 2; h++) {
            const int R = 32 * rg + 16 * mi + 8 * h + lq;
            const int e = base + R;
            const bool v = vr[mi * 2 + h];
            float2 p0 = *(float2*)(smem + (sLN - sb) + (uint32_t)R * 8);
            float2 p1 = *(float2*)(smem + (sLN - sb) + (uint32_t)(128 + R) * 8);
            float2 p2 = *(float2*)(smem + (sLN - sb) + (uint32_t)(256 + R) * 8);
            float2 p3 = *(float2*)(smem + (sLN - sb) + (uint32_t)(384 + R) * 8);
            const float mu  = (p0.x + p1.x + p2.x + p3.x) * 0.0078125f;
            const float var = (p0.y + p1.y + p2.y + p3.y) * 0.0078125f - mu * mu;
            const float rs  = rsqrtf(var + 1e-5f);
            const float4* pe = (const float4*)(efeat + (size_t)(v ? e : 0) * 128 + Lb);
            float4 r0 = v ? __ldg(pe)     : make_float4(0.f, 0.f, 0.f, 0.f);
            float4 r1 = v ? __ldg(pe + 1) : make_float4(0.f, 0.f, 0.f, 0.f);
            float4 o0, o1;
            o0.x = (ACCJ(mi, h, 0) - mu) * rs * ga0.x + be0.x + r0.x;
            o0.y = (ACCJ(mi, h, 1) - mu) * rs * ga0.y + be0.y + r0.y;
            o0.z = (ACCJ(mi, h, 2) - mu) * rs * ga0.z + be0.z + r0.z;
            o0.w = (ACCJ(mi, h, 3) - mu) * rs * ga0.w + be0.w + r0.w;
            o1.x = (ACCJ(mi, h, 4) - mu) * rs * ga1.x + be1.x + r1.x;
            o1.y = (ACCJ(mi, h, 5) - mu) * rs * ga1.y + be1.y + r1.y;
            o1.z = (ACCJ(mi, h, 6) - mu) * rs * ga1.z + be1.z + r1.z;
            o1.w = (ACCJ(mi, h, 7) - mu) * rs * ga1.w + be1.w + r1.w;
            if (v) {
                float4* po = (float4*)(out + (size_t)e * 128 + Lb);
                po[0] = o0; po[1] = o1;
            }
        }

        // complete the nfeat passthrough slice
        if (cvalid) ((float4*)nfeat_out)[cidx] = cpy;

        ph ^= 1;
    }
}

// ---------------- launch ----------------

extern "C" void kernel_launch(void* const* d_in, const int* in_sizes, int n_in,
                              void* d_out, int out_size) {
    const float* efeat = (const float*)d_in[0];
    const float* nfeat = (const float*)d_in[1];
    const int*   src   = (const int*)d_in[2];
    const int*   dst   = (const int*)d_in[3];
    const float* We    = (const float*)d_in[4];
    const float* Ws    = (const float*)d_in[5];
    const float* Wd    = (const float*)d_in[6];
    const float* b1    = (const float*)d_in[7];
    const float* Wo    = (const float*)d_in[8];
    const float* bo    = (const float*)d_in[9];
    const float* gamma = (const float*)d_in[10];
    const float* beta  = (const float*)d_in[11];
    float* out = (float*)d_out;

    cudaFuncSetAttribute(node_kernel, cudaFuncAttributeMaxDynamicSharedMemorySize, NODE_SMEM);
    cudaFuncSetAttribute(edge_kernel, cudaFuncAttributeMaxDynamicSharedMemorySize, EDGE_SMEM);

    node_kernel<<<NTILES, 512, NODE_SMEM>>>(nfeat, Ws, Wd, b1);
    edge_kernel<<<GRID_E, 512, EDGE_SMEM>>>(efeat, src, dst, We, Wo, bo, gamma, beta,
                                            nfeat, out + (size_t)N_EDGES * 128, out);
}

// round 16
// speedup vs baseline: 1.0752x; 1.0501x over previous
#include <cuda_runtime.h>
#include <cuda_fp16.h>
#include <cstdint>

#define DEVINL static __device__ __forceinline__

#define N_EDGES 600000
#define N_NODES 50000
#define ETILES 4688     // ceil(600000/128)
#define NTILES 391      // ceil(50000/128)
#define GRID_E 148

// fp16 tile geometry: 128 rows x 128 cols, row stride 272B (136 halfs).
// 272/4 = 68 ≡ 4 (mod 32) => conflict-free for the mma fragment pattern;
// and 272/16 = 17 ≡ 1 (mod 8) => the 8 16B rows of each ldmatrix 8x8 matrix
// hit 8 distinct 16B bank groups (conflict-free ldmatrix).
#define RS16 272
#define T16_BYTES (128 * RS16)      // 34816
// fp32 staging tile for cp.async efeat prefetch (plain 512B rows).
#define RSTG 512
#define STG_BYTES (128 * RSTG)      // 65536

// Node projection scratch in FP16 (b1 folded into srcproj): 2 x 12.8MB ->
// both tables fully L2-resident, gathers are one LDG.128/row.
static __device__ uint16_t g_srcproj[(size_t)N_NODES * 128];
static __device__ uint16_t g_dstproj[(size_t)N_NODES * 128];

// ---------------- helpers ----------------

DEVINL uint32_t smem_u32(const void* p) {
    uint32_t a;
    asm("{ .reg .u64 t; cvta.to.shared.u64 t, %1; cvt.u32.u64 %0, t; }" : "=r"(a) : "l"(p));
    return a;
}
DEVINL uint32_t packh2(float lo, float hi) {
    uint32_t r;
    asm("cvt.rn.f16x2.f32 %0, %1, %2;" : "=r"(r) : "f"(hi), "f"(lo));
    return r;
}
DEVINL float2 h2f2(uint32_t h) {
    return __half22float2(*reinterpret_cast<const __half2*>(&h));
}
DEVINL float4 lds128f(uint32_t a) {
    float4 v;
    asm volatile("ld.shared.v4.f32 {%0,%1,%2,%3}, [%4];"
                 : "=f"(v.x), "=f"(v.y), "=f"(v.z), "=f"(v.w) : "r"(a));
    return v;
}
DEVINL void sts64f(uint32_t a, float x, float y) {
    asm volatile("st.shared.v2.f32 [%0], {%1,%2};" :: "r"(a), "f"(x), "f"(y));
}
DEVINL void sts64(uint32_t a, uint32_t x, uint32_t y) {
    asm volatile("st.shared.v2.b32 [%0], {%1,%2};" :: "r"(a), "r"(x), "r"(y));
}
DEVINL void sts128(uint32_t a, uint32_t x, uint32_t y, uint32_t z, uint32_t w) {
    asm volatile("st.shared.v4.b32 [%0], {%1,%2,%3,%4};" :: "r"(a), "r"(x), "r"(y), "r"(z), "r"(w));
}
DEVINL void cpasync16(uint32_t s, const void* g, int srcbytes) {
    asm volatile("cp.async.cg.shared.global [%0], [%1], 16, %2;"
                 :: "r"(s), "l"(g), "r"(srcbytes));
}
DEVINL void cpcommit() { asm volatile("cp.async.commit_group;" ::: "memory"); }
DEVINL void cpwait0()  { asm volatile("cp.async.wait_group 0;" ::: "memory"); }

// mbarrier-based group sync (R11; avoids BAR hw which faulted in R9/R10).
DEVINL void mbar_init(uint32_t a, uint32_t cnt) {
    asm volatile("mbarrier.init.shared.b64 [%0], %1;" :: "r"(a), "r"(cnt) : "memory");
}
DEVINL void gsync(uint32_t mb, uint32_t ph) {
    asm volatile(
        "{\n\t.reg .pred P;\n\t"
        "mbarrier.arrive.shared.b64 _, [%0];\n\t"
        "LW%=:\n\t"
        "mbarrier.try_wait.parity.acquire.cta.shared::cta.b64 P, [%0], %1, 0x989680;\n\t"
        "@P bra.uni LD%=;\n\t"
        "bra.uni LW%=;\n\t"
        "LD%=:\n\t}"
        :: "r"(mb), "r"(ph) : "memory");
}

// silu(x) = x*sigmoid(x) = h + h*tanh(h), h = x/2  (1 MUFU)
DEVINL float silu_f(float x) {
    float h = 0.5f * x, t;
    asm("tanh.approx.f32 %0, %1;" : "=f"(t) : "f"(h));
    return fmaf(h, t, h);
}

// Out-dim permutation: thread's D-frag cols become CONTIGUOUS 32*cg+8*lm+{0..7}.
DEVINL int permn(int n) {
    return (n & 0x61) | ((n & 6) << 2) | ((n >> 2) & 6);
}

// fp16 tile address: row r, BYTE column cb.
DEVINL uint32_t adr16(uint32_t b, int r, int cb) {
    return b + (uint32_t)r * (uint32_t)RS16 + (uint32_t)cb;
}

// m16n8k16 fp16 HMMA, fp32 accum (base-target PTX, sm_80+)
DEVINL void mma16(float* d, const uint32_t* a, uint32_t b0, uint32_t b1) {
    asm volatile(
        "mma.sync.aligned.m16n8k16.row.col.f32.f16.f16.f32 "
        "{%0,%1,%2,%3}, {%4,%5,%6,%7}, {%8,%9}, {%0,%1,%2,%3};"
        : "+f"(d[0]), "+f"(d[1]), "+f"(d[2]), "+f"(d[3])
        : "r"(a[0]), "r"(a[1]), "r"(a[2]), "r"(a[3]), "r"(b0), "r"(b1));
}

// ldmatrix x4: four 8x8 b16 matrices; lanes 8j..8j+7 address matrix j's rows.
DEVINL void ldm4(uint32_t addr, uint32_t* r) {
    asm volatile("ldmatrix.sync.aligned.m8n8.x4.shared.b16 {%0,%1,%2,%3}, [%4];"
                 : "=r"(r[0]), "=r"(r[1]), "=r"(r[2]), "=r"(r[3]) : "r"(addr));
}

// Load [128 out][128 in] row-major fp32 weight into fp16 SMEM (out-rows permuted).
DEVINL void load_weight16(uint32_t sbW, const float* __restrict__ W, int tid) {
#pragma unroll 1
    for (int i = tid; i < 4096; i += 512) {
        int n = i >> 5, k4 = (i & 31) << 2;
        float4 v = __ldg((const float4*)W + i);
        sts64(adr16(sbW, permn(n), k4 * 2), packh2(v.x, v.y), packh2(v.z, v.w));
    }
}

// 128x128x128 fp16 GEMM via ldmatrix, 16 warps. Warp w: rg=w>>2 rows [32rg,+32),
// cg=w&3 cols [32cg,+32). 8 k-steps of 16. acc[(mi*4+nt)*4 + 2*h + e] (fp32).
// A x4 matrices (per mi): {rows0-7 k0-7, rows8-15 k0-7, rows0-7 k8-15, rows8-15 k8-15}
//   -> exactly mma's {a0,a1,a2,a3}.
// B x4 matrices (per nt-pair): {ntA k0-7, ntA k8-15, ntB k0-7, ntB k8-15}
//   non-trans distribution (lane l <- row l/4, halfs 2(l%4)) == mma B fragment.
DEVINL void gemm16(uint32_t sbA, uint32_t sbW, int rg, int cg, int lane,
                   float acc[32]) {
    const int m = lane >> 3, i = lane & 7;
    uint32_t aA0 = adr16(sbA, 32 * rg + ((m & 1) << 3) + i, (m >> 1) << 4);
    uint32_t aA1 = aA0 + 16 * RS16;
    uint32_t aB0 = adr16(sbW, 32 * cg + ((m >> 1) << 3) + i, (m & 1) << 4);
    uint32_t aB1 = aB0 + 16 * RS16;
#pragma unroll
    for (int kk = 0; kk < 8; kk++) {
        uint32_t a0[4], a1[4], b0[4], b1[4];
        ldm4(aA0, a0);   // mi=0: a0..a3
        ldm4(aA1, a1);   // mi=1
        ldm4(aB0, b0);   // {nt0.b0, nt0.b1, nt1.b0, nt1.b1}
        ldm4(aB1, b1);   // {nt2.b0, nt2.b1, nt3.b0, nt3.b1}
        aA0 += 32; aA1 += 32; aB0 += 32; aB1 += 32;
        mma16(acc + 0,  a0, b0[0], b0[1]);
        mma16(acc + 16, a1, b0[0], b0[1]);
        mma16(acc + 4,  a0, b0[2], b0[3]);
        mma16(acc + 20, a1, b0[2], b0[3]);
        mma16(acc + 8,  a0, b1[0], b1[1]);
        mma16(acc + 24, a1, b1[0], b1[1]);
        mma16(acc + 12, a0, b1[2], b1[3]);
        mma16(acc + 28, a1, b1[2], b1[3]);
    }
}

#define ACCJ(mi, h, j) acc[((mi) * 4 + ((j) >> 1)) * 4 + 2 * (h) + ((j) & 1)]

// ---------------- node projection kernel ----------------
// SMEM: Ws16[0,34816) Wd16[34816,69632) A16[69632,104448) b1[104448,+512)
#define NODE_SMEM 104960

__global__ void __launch_bounds__(512, 1)
node_kernel(const float* __restrict__ nfeat, const float* __restrict__ Ws,
            const float* __restrict__ Wd, const float* __restrict__ b1,
            float* __restrict__ nfeat_out) {
    extern __shared__ char smem[];
    const uint32_t sb = smem_u32(smem);
    const uint32_t sWS = sb, sWD = sb + T16_BYTES, sA = sb + 2 * T16_BYTES;
    const uint32_t sB1 = sb + 3 * T16_BYTES;
    const int tid = threadIdx.x, w = tid >> 5, lane = tid & 31;
    const int lq = lane >> 2, lm = lane & 3, rg = w >> 2, cg = w & 3;

    load_weight16(sWS, Ws, tid);
    load_weight16(sWD, Wd, tid);
    if (tid < 128) ((float*)(smem + 3 * T16_BYTES))[tid] = __ldg(b1 + tid);

    const int base = blockIdx.x * 128;
#pragma unroll
    for (int i = 0; i < 8; i++) {
        const int f4 = tid + 512 * i;
        const int row = f4 >> 5, c4 = f4 & 31;
        const int ng = base + row;
        const bool v = ng < N_NODES;
        float4 x = v ? __ldg((const float4*)(nfeat + (size_t)ng * 128) + c4)
                     : make_float4(0.f, 0.f, 0.f, 0.f);
        if (v) *((float4*)(nfeat_out + (size_t)ng * 128) + c4) = x;  // passthrough
        sts64(adr16(sA, row, c4 * 8), packh2(x.x, x.y), packh2(x.z, x.w));
    }
    __syncthreads();

    const int Lb = 32 * cg + 8 * lm;                 // thread's logical col base
    const float4 bb0 = lds128f(sB1 + (uint32_t)Lb * 4);
    const float4 bb1 = lds128f(sB1 + (uint32_t)Lb * 4 + 16);

    float acc[32];
#pragma unroll
    for (int i = 0; i < 32; i++) acc[i] = 0.f;
    gemm16(sA, sWS, rg, cg, lane, acc);
#pragma unroll
    for (int mi = 0; mi < 2; mi++)
#pragma unroll
    for (int h = 0; h < 2; h++) {
        const int ng = base + 32 * rg + 16 * mi + 8 * h + lq;
        if (ng < N_NODES) {
            uint4 o;
            o.x = packh2(ACCJ(mi, h, 0) + bb0.x, ACCJ(mi, h, 1) + bb0.y);
            o.y = packh2(ACCJ(mi, h, 2) + bb0.z, ACCJ(mi, h, 3) + bb0.w);
            o.z = packh2(ACCJ(mi, h, 4) + bb1.x, ACCJ(mi, h, 5) + bb1.y);
            o.w = packh2(ACCJ(mi, h, 6) + bb1.z, ACCJ(mi, h, 7) + bb1.w);
            *(uint4*)(g_srcproj + (size_t)ng * 128 + Lb) = o;
        }
    }

#pragma unroll
    for (int i = 0; i < 32; i++) acc[i] = 0.f;
    gemm16(sA, sWD, rg, cg, lane, acc);
#pragma unroll
    for (int mi = 0; mi < 2; mi++)
#pragma unroll
    for (int h = 0; h < 2; h++) {
        const int ng = base + 32 * rg + 16 * mi + 8 * h + lq;
        if (ng < N_NODES) {
            uint4 o;
            o.x = packh2(ACCJ(mi, h, 0), ACCJ(mi, h, 1));
            o.y = packh2(ACCJ(mi, h, 2), ACCJ(mi, h, 3));
            o.z = packh2(ACCJ(mi, h, 4), ACCJ(mi, h, 5));
            o.w = packh2(ACCJ(mi, h, 6), ACCJ(mi, h, 7));
            *(uint4*)(g_dstproj + (size_t)ng * 128 + Lb) = o;
        }
    }
}

// ---------------- fused edge kernel (persistent, 512 thr) ----------------
// SMEM: We16[0,34816) Wo16[34816,69632) A16[69632,104448) STG[104448,169984)
//       LN[169984,+4096) bo@174080 gamma@174592 beta@175104 mbar@175616(+128)
#define EDGE_SMEM 175744

// Group-local prefetch of NEXT tile's efeat (raw fp32) into the staging buffer.
DEVINL void prefetch_efeat_grp(uint32_t sSTG, const float* __restrict__ efeat,
                               int tile, int rg, int gt) {
    const int base = tile * 128 + 32 * rg;
#pragma unroll
    for (int i = 0; i < 8; i++) {
        const int f4 = gt + 128 * i;
        const int row = f4 >> 5, c4 = f4 & 31;
        const int e = base + row;
        const bool v = e < N_EDGES;
        const float* g = efeat + (size_t)(v ? e : 0) * 128 + c4 * 4;
        cpasync16(sSTG + (uint32_t)(32 * rg + row) * RSTG + (uint32_t)c4 * 16u,
                  g, v ? 16 : 0);
    }
    cpcommit();
}

// Convert this thread's own staged fp32 bytes -> fp16 A tile.
DEVINL void convert_rows(uint32_t sA16, uint32_t sSTG, int rg, int gt) {
#pragma unroll
    for (int i = 0; i < 8; i++) {
        const int f4 = gt + 128 * i;
        const int row = 32 * rg + (f4 >> 5), c4 = f4 & 31;
        float4 v = lds128f(sSTG + (uint32_t)row * RSTG + (uint32_t)c4 * 16u);
        sts64(adr16(sA16, row, c4 * 8), packh2(v.x, v.y), packh2(v.z, v.w));
    }
}

__global__ void __launch_bounds__(512, 1)
edge_kernel(const float* __restrict__ efeat, const int* __restrict__ src,
            const int* __restrict__ dst, const float* __restrict__ We,
            const float* __restrict__ Wo, const float* __restrict__ bo,
            const float* __restrict__ gamma, const float* __restrict__ beta,
            float* __restrict__ out) {
    extern __shared__ char smem[];
    const uint32_t sb = smem_u32(smem);
    const uint32_t sWE = sb, sWO = sb + T16_BYTES, sA16 = sb + 2 * T16_BYTES;
    const uint32_t sSTG = sb + 3 * T16_BYTES;
    const uint32_t sLN = sSTG + STG_BYTES;
    const uint32_t sBO = sLN + 4096, sGA = sBO + 512, sBE = sGA + 512;
    const uint32_t sMB = sBE + 512;                  // 16 mbarriers
    const int tid = threadIdx.x, w = tid >> 5, lane = tid & 31;
    const int lq = lane >> 2, lm = lane & 3, rg = w >> 2, cg = w & 3;
    const int gt = tid & 127;
    const uint32_t mb0 = sMB + (uint32_t)rg * 32u;

    load_weight16(sWE, We, tid);
    load_weight16(sWO, Wo, tid);
    if (tid < 128) {
        ((float*)(smem + (sBO - sb)))[tid] = __ldg(bo + tid);
        ((float*)(smem + (sGA - sb)))[tid] = __ldg(gamma + tid);
        ((float*)(smem + (sBE - sb)))[tid] = __ldg(beta + tid);
    }
    if (tid < 16) mbar_init(sMB + (uint32_t)tid * 8u, 128);
    prefetch_efeat_grp(sSTG, efeat, blockIdx.x, rg, gt);
    __syncthreads();      // weights/biases/mbarriers visible; groups decouple after

    const int Lb = 32 * cg + 8 * lm;
    const float4 bo0 = lds128f(sBO + (uint32_t)Lb * 4);
    const float4 bo1 = lds128f(sBO + (uint32_t)Lb * 4 + 16);
    const float4 ga0 = lds128f(sGA + (uint32_t)Lb * 4);
    const float4 ga1 = lds128f(sGA + (uint32_t)Lb * 4 + 16);
    const float4 be0 = lds128f(sBE + (uint32_t)Lb * 4);
    const float4 be1 = lds128f(sBE + (uint32_t)Lb * 4 + 16);

    uint32_t ph = 0;

    for (int tile = blockIdx.x; tile < ETILES; tile += GRID_E) {
        const int base = tile * 128;
        cpwait0();
        convert_rows(sA16, sSTG, rg, gt);     // staged fp32 -> fp16 A tile
        gsync(mb0 + 0, ph);                   // (a) group's 32 A16 rows ready

        // STG is dead after (a) (only convert reads it) -> issue next tile's
        // prefetch NOW; it gets the whole tile to complete.
        if (tile + GRID_E < ETILES)
            prefetch_efeat_grp(sSTG, efeat, tile + GRID_E, rg, gt);

        // Indices + all gather loads now (latency hides under GEMM1).
        bool vr[4];
        uint4 sg[4], dg[4];
#pragma unroll
        for (int mi = 0; mi < 2; mi++)
#pragma unroll
        for (int h = 0; h < 2; h++) {
            const int e = base + 32 * rg + 16 * mi + 8 * h + lq;
            const bool v = e < N_EDGES;
            vr[mi * 2 + h] = v;
            const int si = v ? __ldg(src + e) : 0;
            const int di = v ? __ldg(dst + e) : 0;
            sg[mi * 2 + h] = __ldg((const uint4*)(g_srcproj + (size_t)si * 128 + Lb));
            dg[mi * 2 + h] = __ldg((const uint4*)(g_dstproj + (size_t)di * 128 + Lb));
        }

        float acc[32];
#pragma unroll
        for (int i = 0; i < 32; i++) acc[i] = 0.f;
        gemm16(sA16, sWE, rg, cg, lane, acc);     // h-pre = efeat @ We^T
        gsync(mb0 + 8, ph);                   // (c) group done reading its A rows

        // epilogue1: + srcproj (b1 folded) + dstproj, SiLU, act -> A16
#pragma unroll
        for (int mi = 0; mi < 2; mi++)
#pragma unroll
        for (int h = 0; h < 2; h++) {
            const int R = 32 * rg + 16 * mi + 8 * h + lq;
            const uint4 sv = sg[mi * 2 + h], dv = dg[mi * 2 + h];
            float2 s0 = h2f2(sv.x), s1 = h2f2(sv.y), s2 = h2f2(sv.z), s3 = h2f2(sv.w);
            float2 d0 = h2f2(dv.x), d1 = h2f2(dv.y), d2 = h2f2(dv.z), d3 = h2f2(dv.w);
            float x0 = silu_f(ACCJ(mi, h, 0) + s0.x + d0.x);
            float x1 = silu_f(ACCJ(mi, h, 1) + s0.y + d0.y);
            float x2 = silu_f(ACCJ(mi, h, 2) + s1.x + d1.x);
            float x3 = silu_f(ACCJ(mi, h, 3) + s1.y + d1.y);
            float x4 = silu_f(ACCJ(mi, h, 4) + s2.x + d2.x);
            float x5 = silu_f(ACCJ(mi, h, 5) + s2.y + d2.y);
            float x6 = silu_f(ACCJ(mi, h, 6) + s3.x + d3.x);
            float x7 = silu_f(ACCJ(mi, h, 7) + s3.y + d3.y);
            sts128(adr16(sA16, R, Lb * 2),
                   packh2(x0, x1), packh2(x2, x3), packh2(x4, x5), packh2(x6, x7));
        }
        gsync(mb0 + 16, ph);                  // (d) group's act rows complete

#pragma unroll
        for (int i = 0; i < 32; i++) acc[i] = 0.f;
        gemm16(sA16, sWO, rg, cg, lane, acc);     // o-pre = act @ Wo^T

        // epilogue2a: + bo, LayerNorm partials
#pragma unroll
        for (int mi = 0; mi < 2; mi++)
#pragma unroll
        for (int h = 0; h < 2; h++) {
            float s = 0.f, q = 0.f;
#pragma unroll
            for (int j = 0; j < 8; j++) {
                const float b = (j < 4) ? ((const float*)&bo0)[j] : ((const float*)&bo1)[j - 4];
                float x = ACCJ(mi, h, j) + b;
                ACCJ(mi, h, j) = x;
                s += x;
                q += x * x;
            }
            s += __shfl_xor_sync(0xffffffffu, s, 1);
            q += __shfl_xor_sync(0xffffffffu, q, 1);
            s += __shfl_xor_sync(0xffffffffu, s, 2);
            q += __shfl_xor_sync(0xffffffffu, q, 2);
            if (lm == 0) {
                const int R = 32 * rg + 16 * mi + 8 * h + lq;
                sts64f(sLN + (uint32_t)(cg * 128 + R) * 8, s, q);
            }
        }
        gsync(mb0 + 24, ph);                  // (e) LN partials visible

        // epilogue2b: normalize, affine, + residual efeat (L2-hot), store
#pragma unroll
        for (int mi = 0; mi < 2; mi++)
#pragma unroll
        for (int h = 0; h < 2; h++) {
            const int R = 32 * rg + 16 * mi + 8 * h + lq;
            const int e = base + R;
            const bool v = vr[mi * 2 + h];
            float2 p0 = *(float2*)(smem + (sLN - sb) + (uint32_t)R * 8);
            float2 p1 = *(float2*)(smem + (sLN - sb) + (uint32_t)(128 + R) * 8);
            float2 p2 = *(float2*)(smem + (sLN - sb) + (uint32_t)(256 + R) * 8);
            float2 p3 = *(float2*)(smem + (sLN - sb) + (uint32_t)(384 + R) * 8);
            const float mu  = (p0.x + p1.x + p2.x + p3.x) * 0.0078125f;
            const float var = (p0.y + p1.y + p2.y + p3.y) * 0.0078125f - mu * mu;
            const float rs  = rsqrtf(var + 1e-5f);
            const float4* pe = (const float4*)(efeat + (size_t)(v ? e : 0) * 128 + Lb);
            float4 r0 = v ? __ldg(pe)     : make_float4(0.f, 0.f, 0.f, 0.f);
            float4 r1 = v ? __ldg(pe + 1) : make_float4(0.f, 0.f, 0.f, 0.f);
            float4 o0, o1;
            o0.x = (ACCJ(mi, h, 0) - mu) * rs * ga0.x + be0.x + r0.x;
            o0.y = (ACCJ(mi, h, 1) - mu) * rs * ga0.y + be0.y + r0.y;
            o0.z = (ACCJ(mi, h, 2) - mu) * rs * ga0.z + be0.z + r0.z;
            o0.w = (ACCJ(mi, h, 3) - mu) * rs * ga0.w + be0.w + r0.w;
            o1.x = (ACCJ(mi, h, 4) - mu) * rs * ga1.x + be1.x + r1.x;
            o1.y = (ACCJ(mi, h, 5) - mu) * rs * ga1.y + be1.y + r1.y;
            o1.z = (ACCJ(mi, h, 6) - mu) * rs * ga1.z + be1.z + r1.z;
            o1.w = (ACCJ(mi, h, 7) - mu) * rs * ga1.w + be1.w + r1.w;
            if (v) {
                float4* po = (float4*)(out + (size_t)e * 128 + Lb);
                po[0] = o0; po[1] = o1;
            }
        }
        ph ^= 1;
    }
}

// ---------------- launch ----------------

extern "C" void kernel_launch(void* const* d_in, const int* in_sizes, int n_in,
                              void* d_out, int out_size) {
    const float* efeat = (const float*)d_in[0];
    const float* nfeat = (const float*)d_in[1];
    const int*   src   = (const int*)d_in[2];
    const int*   dst   = (const int*)d_in[3];
    const float* We    = (const float*)d_in[4];
    const float* Ws    = (const float*)d_in[5];
    const float* Wd    = (const float*)d_in[6];
    const float* b1    = (const float*)d_in[7];
    const float* Wo    = (const float*)d_in[8];
    const float* bo    = (const float*)d_in[9];
    const float* gamma = (const float*)d_in[10];
    const float* beta  = (const float*)d_in[11];
    float* out = (float*)d_out;

    cudaFuncSetAttribute(node_kernel, cudaFuncAttributeMaxDynamicSharedMemorySize, NODE_SMEM);
    cudaFuncSetAttribute(edge_kernel, cudaFuncAttributeMaxDynamicSharedMemorySize, EDGE_SMEM);

    // node kernel also writes the nfeat passthrough output
    node_kernel<<<NTILES, 512, NODE_SMEM>>>(nfeat, Ws, Wd, b1,
                                            out + (size_t)N_EDGES * 128);
    edge_kernel<<<GRID_E, 512, EDGE_SMEM>>>(efeat, src, dst, We, Wo, bo, gamma, beta, out);
}

// round 17
// speedup vs baseline: 1.1085x; 1.0309x over previous
#include <cuda_runtime.h>
#include <cuda_fp16.h>
#include <cstdint>

#define DEVINL static __device__ __forceinline__

#define N_EDGES 600000
#define N_NODES 50000
#define ETILES 4688     // ceil(600000/128)
#define NTILES 391      // ceil(50000/128)
#define GRID_E 148      // <= 152 SMs at 1 CTA/SM -> all CTAs resident (spin-safe)

// fp16 tile geometry: 128 rows x 128 cols, row stride 272B (136 halfs).
// 272/4 = 68 ≡ 4 (mod 32) => conflict-free for the mma fragment pattern;
// 272/16 = 17 ≡ 1 (mod 8) => ldmatrix 8x8 rows hit 8 distinct 16B groups.
#define RS16 272
#define T16_BYTES (128 * RS16)      // 34816
// fp32 staging tile for cp.async efeat prefetch (plain 512B rows).
#define RSTG 512
#define STG_BYTES (128 * RSTG)      // 65536

// Node projection tables in FP16 (b1 folded into srcproj): 2 x 12.8MB ->
// L2-resident, gathers are one LDG.128/row.
static __device__ uint16_t g_srcproj[(size_t)N_NODES * 128];
static __device__ uint16_t g_dstproj[(size_t)N_NODES * 128];
// Device-wide epoch barrier: monotone counter, graph-replay safe (no reset).
static __device__ int g_done = 0;

// ---------------- helpers ----------------

DEVINL uint32_t smem_u32(const void* p) {
    uint32_t a;
    asm("{ .reg .u64 t; cvta.to.shared.u64 t, %1; cvt.u32.u64 %0, t; }" : "=r"(a) : "l"(p));
    return a;
}
DEVINL uint32_t packh2(float lo, float hi) {
    uint32_t r;
    asm("cvt.rn.f16x2.f32 %0, %1, %2;" : "=r"(r) : "f"(hi), "f"(lo));
    return r;
}
DEVINL float2 h2f2(uint32_t h) {
    return __half22float2(*reinterpret_cast<const __half2*>(&h));
}
DEVINL float4 lds128f(uint32_t a) {
    float4 v;
    asm volatile("ld.shared.v4.f32 {%0,%1,%2,%3}, [%4];"
                 : "=f"(v.x), "=f"(v.y), "=f"(v.z), "=f"(v.w) : "r"(a));
    return v;
}
DEVINL void sts64f(uint32_t a, float x, float y) {
    asm volatile("st.shared.v2.f32 [%0], {%1,%2};" :: "r"(a), "f"(x), "f"(y));
}
DEVINL void sts64(uint32_t a, uint32_t x, uint32_t y) {
    asm volatile("st.shared.v2.b32 [%0], {%1,%2};" :: "r"(a), "r"(x), "r"(y));
}
DEVINL void sts128(uint32_t a, uint32_t x, uint32_t y, uint32_t z, uint32_t w) {
    asm volatile("st.shared.v4.b32 [%0], {%1,%2,%3,%4};" :: "r"(a), "r"(x), "r"(y), "r"(z), "r"(w));
}
DEVINL void cpasync16(uint32_t s, const void* g, int srcbytes) {
    asm volatile("cp.async.cg.shared.global [%0], [%1], 16, %2;"
                 :: "r"(s), "l"(g), "r"(srcbytes));
}
DEVINL void cpcommit() { asm volatile("cp.async.commit_group;" ::: "memory"); }
DEVINL void cpwait0()  { asm volatile("cp.async.wait_group 0;" ::: "memory"); }

// mbarrier-based group sync (R11; avoids BAR hw which faulted in R9/R10).
DEVINL void mbar_init(uint32_t a, uint32_t cnt) {
    asm volatile("mbarrier.init.shared.b64 [%0], %1;" :: "r"(a), "r"(cnt) : "memory");
}
DEVINL void gsync(uint32_t mb, uint32_t ph) {
    asm volatile(
        "{\n\t.reg .pred P;\n\t"
        "mbarrier.arrive.shared.b64 _, [%0];\n\t"
        "LW%=:\n\t"
        "mbarrier.try_wait.parity.acquire.cta.shared::cta.b64 P, [%0], %1, 0x989680;\n\t"
        "@P bra.uni LD%=;\n\t"
        "bra.uni LW%=;\n\t"
        "LD%=:\n\t}"
        :: "r"(mb), "r"(ph) : "memory");
}

// silu(x) = x*sigmoid(x) = h + h*tanh(h), h = x/2  (1 MUFU)
DEVINL float silu_f(float x) {
    float h = 0.5f * x, t;
    asm("tanh.approx.f32 %0, %1;" : "=f"(t) : "f"(h));
    return fmaf(h, t, h);
}

// Out-dim permutation: thread's D-frag cols become CONTIGUOUS 32*cg+8*lm+{0..7}.
DEVINL int permn(int n) {
    return (n & 0x61) | ((n & 6) << 2) | ((n >> 2) & 6);
}

// fp16 tile address: row r, BYTE column cb.
DEVINL uint32_t adr16(uint32_t b, int r, int cb) {
    return b + (uint32_t)r * (uint32_t)RS16 + (uint32_t)cb;
}

// m16n8k16 fp16 HMMA, fp32 accum (base-target PTX, sm_80+)
DEVINL void mma16(float* d, const uint32_t* a, uint32_t b0, uint32_t b1) {
    asm volatile(
        "mma.sync.aligned.m16n8k16.row.col.f32.f16.f16.f32 "
        "{%0,%1,%2,%3}, {%4,%5,%6,%7}, {%8,%9}, {%0,%1,%2,%3};"
        : "+f"(d[0]), "+f"(d[1]), "+f"(d[2]), "+f"(d[3])
        : "r"(a[0]), "r"(a[1]), "r"(a[2]), "r"(a[3]), "r"(b0), "r"(b1));
}

// ldmatrix x4: four 8x8 b16 matrices; lanes 8j..8j+7 address matrix j's rows.
DEVINL void ldm4(uint32_t addr, uint32_t* r) {
    asm volatile("ldmatrix.sync.aligned.m8n8.x4.shared.b16 {%0,%1,%2,%3}, [%4];"
                 : "=r"(r[0]), "=r"(r[1]), "=r"(r[2]), "=r"(r[3]) : "r"(addr));
}

// Load [128 out][128 in] row-major fp32 weight into fp16 SMEM (out-rows permuted).
DEVINL void load_weight16(uint32_t sbW, const float* __restrict__ W, int tid) {
#pragma unroll 1
    for (int i = tid; i < 4096; i += 512) {
        int n = i >> 5, k4 = (i & 31) << 2;
        float4 v = __ldg((const float4*)W + i);
        sts64(adr16(sbW, permn(n), k4 * 2), packh2(v.x, v.y), packh2(v.z, v.w));
    }
}

// 128x128x128 fp16 GEMM via ldmatrix (R16).
DEVINL void gemm16(uint32_t sbA, uint32_t sbW, int rg, int cg, int lane,
                   float acc[32]) {
    const int m = lane >> 3, i = lane & 7;
    uint32_t aA0 = adr16(sbA, 32 * rg + ((m & 1) << 3) + i, (m >> 1) << 4);
    uint32_t aA1 = aA0 + 16 * RS16;
    uint32_t aB0 = adr16(sbW, 32 * cg + ((m >> 1) << 3) + i, (m & 1) << 4);
    uint32_t aB1 = aB0 + 16 * RS16;
#pragma unroll
    for (int kk = 0; kk < 8; kk++) {
        uint32_t a0[4], a1[4], b0[4], b1[4];
        ldm4(aA0, a0);
        ldm4(aA1, a1);
        ldm4(aB0, b0);
        ldm4(aB1, b1);
        aA0 += 32; aA1 += 32; aB0 += 32; aB1 += 32;
        mma16(acc + 0,  a0, b0[0], b0[1]);
        mma16(acc + 16, a1, b0[0], b0[1]);
        mma16(acc + 4,  a0, b0[2], b0[3]);
        mma16(acc + 20, a1, b0[2], b0[3]);
        mma16(acc + 8,  a0, b1[0], b1[1]);
        mma16(acc + 24, a1, b1[0], b1[1]);
        mma16(acc + 12, a0, b1[2], b1[3]);
        mma16(acc + 28, a1, b1[2], b1[3]);
    }
}

#define ACCJ(mi, h, j) acc[((mi) * 4 + ((j) >> 1)) * 4 + 2 * (h) + ((j) & 1)]

// ---------------- fused persistent kernel (512 thr, 148 CTAs) ----------------
// SMEM: W0[0,34816) W1[34816,69632) A16[69632,104448) STG[104448,169984)
//       LN[169984,+4096) bo@174080 gamma@174592 beta@175104 mbar@175616(+128)
#define FUSED_SMEM 175744

// Group-local prefetch of a tile's efeat (raw fp32) into the staging buffer.
DEVINL void prefetch_efeat_grp(uint32_t sSTG, const float* __restrict__ efeat,
                               int tile, int rg, int gt) {
    const int base = tile * 128 + 32 * rg;
#pragma unroll
    for (int i = 0; i < 8; i++) {
        const int f4 = gt + 128 * i;
        const int row = f4 >> 5, c4 = f4 & 31;
        const int e = base + row;
        const bool v = e < N_EDGES;
        const float* g = efeat + (size_t)(v ? e : 0) * 128 + c4 * 4;
        cpasync16(sSTG + (uint32_t)(32 * rg + row) * RSTG + (uint32_t)c4 * 16u,
                  g, v ? 16 : 0);
    }
    cpcommit();
}

// Convert this thread's own staged fp32 bytes -> fp16 A tile.
DEVINL void convert_rows(uint32_t sA16, uint32_t sSTG, int rg, int gt) {
#pragma unroll
    for (int i = 0; i < 8; i++) {
        const int f4 = gt + 128 * i;
        const int row = 32 * rg + (f4 >> 5), c4 = f4 & 31;
        float4 v = lds128f(sSTG + (uint32_t)row * RSTG + (uint32_t)c4 * 16u);
        sts64(adr16(sA16, row, c4 * 8), packh2(v.x, v.y), packh2(v.z, v.w));
    }
}

__global__ void __launch_bounds__(512, 1)
fused_kernel(const float* __restrict__ efeat, const int* __restrict__ src,
             const int* __restrict__ dst, const float* __restrict__ We,
             const float* __restrict__ Wo, const float* __restrict__ bo,
             const float* __restrict__ gamma, const float* __restrict__ beta,
             const float* __restrict__ nfeat, const float* __restrict__ Ws,
             const float* __restrict__ Wd, const float* __restrict__ b1,
             float* __restrict__ nfeat_out, float* __restrict__ out) {
    extern __shared__ char smem[];
    const uint32_t sb = smem_u32(smem);
    const uint32_t sW0 = sb, sW1 = sb + T16_BYTES, sA16 = sb + 2 * T16_BYTES;
    const uint32_t sSTG = sb + 3 * T16_BYTES;
    const uint32_t sLN = sSTG + STG_BYTES;
    const uint32_t sBO = sLN + 4096, sGA = sBO + 512, sBE = sGA + 512;
    const uint32_t sMB = sBE + 512;                  // 16 mbarriers
    const int tid = threadIdx.x, w = tid >> 5, lane = tid & 31;
    const int lq = lane >> 2, lm = lane & 3, rg = w >> 2, cg = w & 3;
    const int gt = tid & 127;
    const uint32_t mb0 = sMB + (uint32_t)rg * 32u;
    const int Lb = 32 * cg + 8 * lm;

    // ================= Phase 1: node projections =================
    load_weight16(sW0, Ws, tid);
    load_weight16(sW1, Wd, tid);
    if (tid < 128) ((float*)(smem + (sBO - sb)))[tid] = __ldg(b1 + tid);
    __syncthreads();
    {
        const float4 bb0 = lds128f(sBO + (uint32_t)Lb * 4);
        const float4 bb1 = lds128f(sBO + (uint32_t)Lb * 4 + 16);
#pragma unroll 1
        for (int t = blockIdx.x; t < NTILES; t += GRID_E) {
            const int nb = t * 128;
#pragma unroll
            for (int i = 0; i < 8; i++) {
                const int f4 = tid + 512 * i;
                const int row = f4 >> 5, c4 = f4 & 31;
                const int ng = nb + row;
                const bool v = ng < N_NODES;
                float4 x = v ? __ldg((const float4*)(nfeat + (size_t)ng * 128) + c4)
                             : make_float4(0.f, 0.f, 0.f, 0.f);
                if (v) *((float4*)(nfeat_out + (size_t)ng * 128) + c4) = x;
                sts64(adr16(sA16, row, c4 * 8), packh2(x.x, x.y), packh2(x.z, x.w));
            }
            __syncthreads();

            float acc[32];
#pragma unroll
            for (int i = 0; i < 32; i++) acc[i] = 0.f;
            gemm16(sA16, sW0, rg, cg, lane, acc);
#pragma unroll
            for (int mi = 0; mi < 2; mi++)
#pragma unroll
            for (int h = 0; h < 2; h++) {
                const int ng = nb + 32 * rg + 16 * mi + 8 * h + lq;
                if (ng < N_NODES) {
                    uint4 o;
                    o.x = packh2(ACCJ(mi, h, 0) + bb0.x, ACCJ(mi, h, 1) + bb0.y);
                    o.y = packh2(ACCJ(mi, h, 2) + bb0.z, ACCJ(mi, h, 3) + bb0.w);
                    o.z = packh2(ACCJ(mi, h, 4) + bb1.x, ACCJ(mi, h, 5) + bb1.y);
                    o.w = packh2(ACCJ(mi, h, 6) + bb1.z, ACCJ(mi, h, 7) + bb1.w);
                    *(uint4*)(g_srcproj + (size_t)ng * 128 + Lb) = o;
                }
            }
#pragma unroll
            for (int i = 0; i < 32; i++) acc[i] = 0.f;
            gemm16(sA16, sW1, rg, cg, lane, acc);
#pragma unroll
            for (int mi = 0; mi < 2; mi++)
#pragma unroll
            for (int h = 0; h < 2; h++) {
                const int ng = nb + 32 * rg + 16 * mi + 8 * h + lq;
                if (ng < N_NODES) {
                    uint4 o;
                    o.x = packh2(ACCJ(mi, h, 0), ACCJ(mi, h, 1));
                    o.y = packh2(ACCJ(mi, h, 2), ACCJ(mi, h, 3));
                    o.z = packh2(ACCJ(mi, h, 4), ACCJ(mi, h, 5));
                    o.w = packh2(ACCJ(mi, h, 6), ACCJ(mi, h, 7));
                    *(uint4*)(g_dstproj + (size_t)ng * 128 + Lb) = o;
                }
            }
            __syncthreads();   // A16 free for next node tile
        }
    }

    // ====== Transition: overlap edge setup with other CTAs' node work ======
    load_weight16(sW0, We, tid);
    load_weight16(sW1, Wo, tid);
    if (tid < 128) {
        ((float*)(smem + (sBO - sb)))[tid] = __ldg(bo + tid);
        ((float*)(smem + (sGA - sb)))[tid] = __ldg(gamma + tid);
        ((float*)(smem + (sBE - sb)))[tid] = __ldg(beta + tid);
    }
    if (tid < 16) mbar_init(sMB + (uint32_t)tid * 8u, 128);
    prefetch_efeat_grp(sSTG, efeat, blockIdx.x, rg, gt);

    // Device-wide epoch barrier (monotone counter; graph-replay safe).
    __threadfence();
    __syncthreads();
    if (tid == 0) {
        int ticket = atomicAdd(&g_done, 1);
        int target = (ticket / GRID_E + 1) * GRID_E;
        int v;
        do {
            asm volatile("ld.acquire.gpu.b32 %0, [%1];" : "=r"(v) : "l"(&g_done));
        } while (v < target);
    }
    __syncthreads();
    __threadfence();

    // ================= Phase 2: edge loop (identical to R16) =================
    const float4 bo0 = lds128f(sBO + (uint32_t)Lb * 4);
    const float4 bo1 = lds128f(sBO + (uint32_t)Lb * 4 + 16);
    const float4 ga0 = lds128f(sGA + (uint32_t)Lb * 4);
    const float4 ga1 = lds128f(sGA + (uint32_t)Lb * 4 + 16);
    const float4 be0 = lds128f(sBE + (uint32_t)Lb * 4);
    const float4 be1 = lds128f(sBE + (uint32_t)Lb * 4 + 16);

    uint32_t ph = 0;

    for (int tile = blockIdx.x; tile < ETILES; tile += GRID_E) {
        const int base = tile * 128;
        cpwait0();
        convert_rows(sA16, sSTG, rg, gt);     // staged fp32 -> fp16 A tile
        gsync(mb0 + 0, ph);                   // (a) group's 32 A16 rows ready

        // STG dead after (a) -> issue next tile's prefetch now.
        if (tile + GRID_E < ETILES)
            prefetch_efeat_grp(sSTG, efeat, tile + GRID_E, rg, gt);

        // Indices + all gather loads (latency hides under GEMM1).
        bool vr[4];
        uint4 sg[4], dg[4];
#pragma unroll
        for (int mi = 0; mi < 2; mi++)
#pragma unroll
        for (int h = 0; h < 2; h++) {
            const int e = base + 32 * rg + 16 * mi + 8 * h + lq;
            const bool v = e < N_EDGES;
            vr[mi * 2 + h] = v;
            const int si = v ? __ldg(src + e) : 0;
            const int di = v ? __ldg(dst + e) : 0;
            sg[mi * 2 + h] = __ldg((const uint4*)(g_srcproj + (size_t)si * 128 + Lb));
            dg[mi * 2 + h] = __ldg((const uint4*)(g_dstproj + (size_t)di * 128 + Lb));
        }

        float acc[32];
#pragma unroll
        for (int i = 0; i < 32; i++) acc[i] = 0.f;
        gemm16(sA16, sW0, rg, cg, lane, acc);     // h-pre = efeat @ We^T
        gsync(mb0 + 8, ph);                   // (c) group done reading its A rows

        // epilogue1: + srcproj (b1 folded) + dstproj, SiLU, act -> A16
#pragma unroll
        for (int mi = 0; mi < 2; mi++)
#pragma unroll
        for (int h = 0; h < 2; h++) {
            const int R = 32 * rg + 16 * mi + 8 * h + lq;
            const uint4 sv = sg[mi * 2 + h], dv = dg[mi * 2 + h];
            float2 s0 = h2f2(sv.x), s1 = h2f2(sv.y), s2 = h2f2(sv.z), s3 = h2f2(sv.w);
            float2 d0 = h2f2(dv.x), d1 = h2f2(dv.y), d2 = h2f2(dv.z), d3 = h2f2(dv.w);
            float x0 = silu_f(ACCJ(mi, h, 0) + s0.x + d0.x);
            float x1 = silu_f(ACCJ(mi, h, 1) + s0.y + d0.y);
            float x2 = silu_f(ACCJ(mi, h, 2) + s1.x + d1.x);
            float x3 = silu_f(ACCJ(mi, h, 3) + s1.y + d1.y);
            float x4 = silu_f(ACCJ(mi, h, 4) + s2.x + d2.x);
            float x5 = silu_f(ACCJ(mi, h, 5) + s2.y + d2.y);
            float x6 = silu_f(ACCJ(mi, h, 6) + s3.x + d3.x);
            float x7 = silu_f(ACCJ(mi, h, 7) + s3.y + d3.y);
            sts128(adr16(sA16, R, Lb * 2),
                   packh2(x0, x1), packh2(x2, x3), packh2(x4, x5), packh2(x6, x7));
        }
        gsync(mb0 + 16, ph);                  // (d) group's act rows complete

#pragma unroll
        for (int i = 0; i < 32; i++) acc[i] = 0.f;
        gemm16(sA16, sW1, rg, cg, lane, acc);     // o-pre = act @ Wo^T

        // epilogue2a: + bo, LayerNorm partials
#pragma unroll
        for (int mi = 0; mi < 2; mi++)
#pragma unroll
        for (int h = 0; h < 2; h++) {
            float s = 0.f, q = 0.f;
#pragma unroll
            for (int j = 0; j < 8; j++) {
                const float b = (j < 4) ? ((const float*)&bo0)[j] : ((const float*)&bo1)[j - 4];
                float x = ACCJ(mi, h, j) + b;
                ACCJ(mi, h, j) = x;
                s += x;
                q += x * x;
            }
            s += __shfl_xor_sync(0xffffffffu, s, 1);
            q += __shfl_xor_sync(0xffffffffu, q, 1);
            s += __shfl_xor_sync(0xffffffffu, s, 2);
            q += __shfl_xor_sync(0xffffffffu, q, 2);
            if (lm == 0) {
                const int R = 32 * rg + 16 * mi + 8 * h + lq;
                sts64f(sLN + (uint32_t)(cg * 128 + R) * 8, s, q);
            }
        }
        gsync(mb0 + 24, ph);                  // (e) LN partials visible

        // epilogue2b: normalize, affine, + residual efeat (L2-hot), store
#pragma unroll
        for (int mi = 0; mi < 2; mi++)
#pragma unroll
        for (int h = 0; h < 2; h++) {
            const int R = 32 * rg + 16 * mi + 8 * h + lq;
            const int e = base + R;
            const bool v = vr[mi * 2 + h];
            float2 p0 = *(float2*)(smem + (sLN - sb) + (uint32_t)R * 8);
            float2 p1 = *(float2*)(smem + (sLN - sb) + (uint32_t)(128 + R) * 8);
            float2 p2 = *(float2*)(smem + (sLN - sb) + (uint32_t)(256 + R) * 8);
            float2 p3 = *(float2*)(smem + (sLN - sb) + (uint32_t)(384 + R) * 8);
            const float mu  = (p0.x + p1.x + p2.x + p3.x) * 0.0078125f;
            const float var = (p0.y + p1.y + p2.y + p3.y) * 0.0078125f - mu * mu;
            const float rs  = rsqrtf(var + 1e-5f);
            const float4* pe = (const float4*)(efeat + (size_t)(v ? e : 0) * 128 + Lb);
            float4 r0 = v ? __ldg(pe)     : make_float4(0.f, 0.f, 0.f, 0.f);
            float4 r1 = v ? __ldg(pe + 1) : make_float4(0.f, 0.f, 0.f, 0.f);
            float4 o0, o1;
            o0.x = (ACCJ(mi, h, 0) - mu) * rs * ga0.x + be0.x + r0.x;
            o0.y = (ACCJ(mi, h, 1) - mu) * rs * ga0.y + be0.y + r0.y;
            o0.z = (ACCJ(mi, h, 2) - mu) * rs * ga0.z + be0.z + r0.z;
            o0.w = (ACCJ(mi, h, 3) - mu) * rs * ga0.w + be0.w + r0.w;
            o1.x = (ACCJ(mi, h, 4) - mu) * rs * ga1.x + be1.x + r1.x;
            o1.y = (ACCJ(mi, h, 5) - mu) * rs * ga1.y + be1.y + r1.y;
            o1.z = (ACCJ(mi, h, 6) - mu) * rs * ga1.z + be1.z + r1.z;
            o1.w = (ACCJ(mi, h, 7) - mu) * rs * ga1.w + be1.w + r1.w;
            if (v) {
                float4* po = (float4*)(out + (size_t)e * 128 + Lb);
                po[0] = o0; po[1] = o1;
            }
        }
        ph ^= 1;
    }
}

// ---------------- launch ----------------

extern "C" void kernel_launch(void* const* d_in, const int* in_sizes, int n_in,
                              void* d_out, int out_size) {
    const float* efeat = (const float*)d_in[0];
    const float* nfeat = (const float*)d_in[1];
    const int*   src   = (const int*)d_in[2];
    const int*   dst   = (const int*)d_in[3];
    const float* We    = (const float*)d_in[4];
    const float* Ws    = (const float*)d_in[5];
    const float* Wd    = (const float*)d_in[6];
    const float* b1    = (const float*)d_in[7];
    const float* Wo    = (const float*)d_in[8];
    const float* bo    = (const float*)d_in[9];
    const float* gamma = (const float*)d_in[10];
    const float* beta  = (const float*)d_in[11];
    float* out = (float*)d_out;

    cudaFuncSetAttribute(fused_kernel, cudaFuncAttributeMaxDynamicSharedMemorySize, FUSED_SMEM);

    fused_kernel<<<GRID_E, 512, FUSED_SMEM>>>(
        efeat, src, dst, We, Wo, bo, gamma, beta,
        nfeat, Ws, Wd, b1, out + (size_t)N_EDGES * 128, out);
}